// round 12
// baseline (speedup 1.0000x reference)
#include <cuda_runtime.h>

// Shape fixed by setup_inputs: B=32, N=65536, T=64, HIDDEN=16.
#define BB      32
#define NN      65536
#define TT      64
#define CHUNKS  32                 // chunks per row (2048 cells each)
#define CWORDS  32                 // u64 words per chunk
#define FULLM   0xFFFFFFFFu

typedef unsigned long long u64;

// 3-input mux over constant masks: next_bit = msk[L*4 + C*2 + R].
__device__ __forceinline__ u64 mux3(u64 L, u64 C, u64 R,
                                    u64 m0, u64 m1, u64 m2, u64 m3,
                                    u64 m4, u64 m5, u64 m6, u64 m7) {
    u64 x0 = (R & m1) | (~R & m0);
    u64 x1 = (R & m3) | (~R & m2);
    u64 x2 = (R & m5) | (~R & m4);
    u64 x3 = (R & m7) | (~R & m6);
    u64 y0 = (C & x1) | (~C & x0);
    u64 y1 = (C & x3) | (~C & x2);
    return (L & y1) | (~L & y0);
}

__device__ __forceinline__ u64 pack_word(const float* __restrict__ p) {
    u64 w = 0ULL;
    const float4* p4 = (const float4*)p;
#pragma unroll
    for (int k = 0; k < 16; k++) {
        float4 v = p4[k];
        u64 q = 0ULL;
        if (v.x > 0.5f) q |= 1ULL;
        if (v.y > 0.5f) q |= 2ULL;
        if (v.z > 0.5f) q |= 4ULL;
        if (v.w > 0.5f) q |= 8ULL;
        w |= q << (4 * k);
    }
    return w;
}

// 256-bit streaming store (sm_100a+): one STG.256 instead of two STG.128.
__device__ __forceinline__ void st_v8_cs(float* p,
                                         float a, float b, float c, float d,
                                         float e, float f, float g, float h) {
    asm volatile("st.global.cs.v8.f32 [%0], {%1,%2,%3,%4,%5,%6,%7,%8};"
                 :: "l"(p), "f"(a), "f"(b), "f"(c), "f"(d),
                    "f"(e), "f"(f), "f"(g), "f"(h)
                 : "memory");
}

// R2 champion structure: 8 warps per CTA, each warp owns one chunk of 2048
// cells (one u64 per lane, neighbors via shuffle). Lanes 0/31 carry one u64
// halo word each — 63 steps < 64 halo bits, so beyond-halo garbage never
// reaches the chunk. Store loop now uses 256-bit stores: 8 STG.256 per step
// per lane instead of 16 STG.128 (halves the LSU-issue floor).
__global__ __launch_bounds__(256) void fused_kernel(
    const float* __restrict__ f0,
    const float* __restrict__ W1,   // (3,16)
    const float* __restrict__ b1,   // (16,)
    const float* __restrict__ W2,   // (16,1)
    const float* __restrict__ b2,   // (1,)
    float* __restrict__ out)
{
    __shared__ u64 smsk[8];
    const int tid = threadIdx.x;

    // Collapse the MLP controller to an 8-entry truth table.
    if (tid < 8) {
        const float l = (float)((tid >> 2) & 1);
        const float c = (float)((tid >> 1) & 1);
        const float r = (float)(tid & 1);
        float logit = b2[0];
#pragma unroll
        for (int h = 0; h < 16; h++) {
            float v = fmaf(l, W1[h], fmaf(c, W1[16 + h], fmaf(r, W1[32 + h], b1[h])));
            logit = fmaf(W2[h], fmaxf(v, 0.0f), logit);
        }
        smsk[tid] = (logit > 0.0f) ? ~0ULL : 0ULL;
    }
    __syncthreads();

    const u64 m0 = smsk[0], m1 = smsk[1], m2 = smsk[2], m3 = smsk[3];
    const u64 m4 = smsk[4], m5 = smsk[5], m6 = smsk[6], m7 = smsk[7];

    const int gw   = blockIdx.x * 8 + (tid >> 5);   // global warp id 0..1023
    const int lane = tid & 31;
    const int row  = gw >> 5;                       // batch row
    const int ch   = gw & (CHUNKS - 1);             // chunk within row
    const bool first = (ch == 0), last = (ch == CHUNKS - 1);

    const size_t rowoff = (size_t)row * NN;
    const int cell0 = ch * (CWORDS * 64);           // first cell of chunk

    // ---- t = 0 slab: copy f0 chunk verbatim (v4 loads, v8 stores) ----
    const float4* src4 = (const float4*)(f0 + rowoff + cell0);
    float* dst = out + rowoff + cell0;
#pragma unroll
    for (int k = 0; k < 8; k++) {
        const int idx = k * 32 + lane;              // v8-slot index in chunk
        float4 a = __ldg(src4 + idx * 2);
        float4 b = __ldg(src4 + idx * 2 + 1);
        st_v8_cs(dst + idx * 8, a.x, a.y, a.z, a.w, b.x, b.y, b.z, b.w);
    }

    // ---- pack this lane's word + halo words on lanes 0/31 ----
    u64 cur = pack_word(f0 + rowoff + cell0 + lane * 64);
    u64 hl = 0ULL, hr = 0ULL;
    if (lane == 0 && !first)
        hl = pack_word(f0 + rowoff + cell0 - 64);
    if (lane == 31 && !last)
        hr = pack_word(f0 + rowoff + cell0 + CWORDS * 64);

    // ---- 63 CA steps, emitting the fp32 slab each step ----
    for (int t = 1; t < TT; t++) {
        u64 p = __shfl_up_sync(FULLM, cur, 1);
        u64 n = __shfl_down_sync(FULLM, cur, 1);
        if (lane == 0)  p = hl;
        if (lane == 31) n = hr;

        const u64 L = (cur << 1) | (p >> 63);
        const u64 R = (cur >> 1) | (n << 63);
        const u64 nx = mux3(L, cur, R, m0, m1, m2, m3, m4, m5, m6, m7);

        // Evolve halo words (beyond-halo treated as 0; true row edges stay 0).
        if (lane == 0 && !first) {
            const u64 hL = hl << 1;
            const u64 hR = (hl >> 1) | (cur << 63);
            hl = mux3(hL, hl, hR, m0, m1, m2, m3, m4, m5, m6, m7);
        }
        if (lane == 31 && !last) {
            const u64 hL = (hr << 1) | (cur >> 63);
            const u64 hR = hr >> 1;
            hr = mux3(hL, hr, hR, m0, m1, m2, m3, m4, m5, m6, m7);
        }
        cur = nx;

        // Output: v8 slot #idx covers cells 8*idx..8*idx+7 -> source word
        // idx>>3, byte (idx&7). One shuffle + one byte extract per 32 bytes.
        float* ot = out + (size_t)t * (BB * NN) + rowoff + cell0;
#pragma unroll
        for (int k = 0; k < 8; k++) {
            const int idx = k * 32 + lane;          // 0..255
            const u64 w = __shfl_sync(FULLM, cur, idx >> 3);
            const unsigned int byte = (unsigned int)(w >> ((idx & 7) * 8)) & 0xFFu;
            st_v8_cs(ot + idx * 8,
                     (byte & 1u)   ? 1.0f : 0.0f,
                     (byte & 2u)   ? 1.0f : 0.0f,
                     (byte & 4u)   ? 1.0f : 0.0f,
                     (byte & 8u)   ? 1.0f : 0.0f,
                     (byte & 16u)  ? 1.0f : 0.0f,
                     (byte & 32u)  ? 1.0f : 0.0f,
                     (byte & 64u)  ? 1.0f : 0.0f,
                     (byte & 128u) ? 1.0f : 0.0f);
        }
    }
}

extern "C" void kernel_launch(void* const* d_in, const int* in_sizes, int n_in,
                              void* d_out, int out_size) {
    const float* f0 = (const float*)d_in[0];
    const float* W1 = (const float*)d_in[1];
    const float* b1 = (const float*)d_in[2];
    const float* W2 = (const float*)d_in[3];
    const float* b2 = (const float*)d_in[4];
    float* out = (float*)d_out;

    // Champion R2 launch shape: 32 rows x 32 chunks = 1024 warps,
    // 8 warps per CTA -> 128 CTAs (2 warps per SMSP, balanced).
    fused_kernel<<<128, 256>>>(f0, W1, b1, W2, b2, out);
}

// round 13
// speedup vs baseline: 1.0169x; 1.0169x over previous
#include <cuda_runtime.h>

// Shape fixed by setup_inputs: B=32, N=65536, T=64, HIDDEN=16.
#define BB      32
#define NN      65536
#define TT      64
#define CHUNKS  32                 // chunks per row (2048 cells each)
#define CWORDS  32                 // u64 words per chunk
#define FULLM   0xFFFFFFFFu

typedef unsigned long long u64;

// 3-input mux over constant masks: next_bit = msk[L*4 + C*2 + R].
__device__ __forceinline__ u64 mux3(u64 L, u64 C, u64 R,
                                    u64 m0, u64 m1, u64 m2, u64 m3,
                                    u64 m4, u64 m5, u64 m6, u64 m7) {
    u64 x0 = (R & m1) | (~R & m0);
    u64 x1 = (R & m3) | (~R & m2);
    u64 x2 = (R & m5) | (~R & m4);
    u64 x3 = (R & m7) | (~R & m4 & 0) | (~R & m6);  // placeholder avoided below
    return 0; // never used — see mux3v
}

// (clean version — the one actually used)
__device__ __forceinline__ u64 mux3v(u64 L, u64 C, u64 R,
                                     u64 m0, u64 m1, u64 m2, u64 m3,
                                     u64 m4, u64 m5, u64 m6, u64 m7) {
    u64 x0 = (R & m1) | (~R & m0);
    u64 x1 = (R & m3) | (~R & m2);
    u64 x2 = (R & m5) | (~R & m4);
    u64 x3 = (R & m7) | (~R & m6);
    u64 y0 = (C & x1) | (~C & x0);
    u64 y1 = (C & x3) | (~C & x2);
    return (L & y1) | (~L & y0);
}

__device__ __forceinline__ u64 pack_word(const float* __restrict__ p) {
    u64 w = 0ULL;
    const float4* p4 = (const float4*)p;
#pragma unroll
    for (int k = 0; k < 16; k++) {
        float4 v = p4[k];
        u64 q = 0ULL;
        if (v.x > 0.5f) q |= 1ULL;
        if (v.y > 0.5f) q |= 2ULL;
        if (v.z > 0.5f) q |= 4ULL;
        if (v.w > 0.5f) q |= 8ULL;
        w |= q << (4 * k);
    }
    return w;
}

// One CA step for the warp's chunk (u64/lane, halos on lanes 0/31).
__device__ __forceinline__ void ca_step(
    u64& cur, u64& hl, u64& hr, int lane, bool first, bool last,
    u64 m0, u64 m1, u64 m2, u64 m3, u64 m4, u64 m5, u64 m6, u64 m7)
{
    u64 p = __shfl_up_sync(FULLM, cur, 1);
    u64 n = __shfl_down_sync(FULLM, cur, 1);
    if (lane == 0)  p = hl;
    if (lane == 31) n = hr;

    const u64 L = (cur << 1) | (p >> 63);
    const u64 R = (cur >> 1) | (n << 63);
    const u64 nx = mux3v(L, cur, R, m0, m1, m2, m3, m4, m5, m6, m7);

    if (lane == 0 && !first) {
        const u64 hL = hl << 1;
        const u64 hR = (hl >> 1) | (cur << 63);
        hl = mux3v(hL, hl, hR, m0, m1, m2, m3, m4, m5, m6, m7);
    }
    if (lane == 31 && !last) {
        const u64 hL = (hr << 1) | (cur >> 63);
        const u64 hR = hr >> 1;
        hr = mux3v(hL, hr, hR, m0, m1, m2, m3, m4, m5, m6, m7);
    }
    cur = nx;
}

// Emit the chunk's fp32 slab for one step (champion R2 store path).
__device__ __forceinline__ void emit_slab(
    float* __restrict__ base, u64 cur, int lane)
{
    float4* ot = (float4*)base;
#pragma unroll
    for (int k = 0; k < 16; k++) {
        const int idx = k * 32 + lane;
        const u64 w = __shfl_sync(FULLM, cur, idx >> 4);
        const unsigned int nib = (unsigned int)(w >> ((idx & 15) * 4)) & 0xFu;
        float4 v;
        v.x = (nib & 1u) ? 1.0f : 0.0f;
        v.y = (nib & 2u) ? 1.0f : 0.0f;
        v.z = (nib & 4u) ? 1.0f : 0.0f;
        v.w = (nib & 8u) ? 1.0f : 0.0f;
        __stcs(ot + idx, v);
    }
}

// Temporal split: warps 0-7 (half 0) store t=0..31 for chunks 0..7 of the
// CTA; warps 8-15 (half 1) evolve the SAME chunks silently through t=1..31,
// then store t=32..63. wid%4 -> each SMSP holds 2 warps of each half:
// 4 warps/SMSP balanced, double the stores in flight vs R2, identical
// contiguous per-SM output stream. Compute is duplicated (trivially cheap);
// halo argument unchanged (63 steps < 64 halo bits).
__global__ __launch_bounds__(512) void fused_kernel(
    const float* __restrict__ f0,
    const float* __restrict__ W1,   // (3,16)
    const float* __restrict__ b1,   // (16,)
    const float* __restrict__ W2,   // (16,1)
    const float* __restrict__ b2,   // (1,)
    float* __restrict__ out)
{
    __shared__ u64 smsk[8];
    const int tid = threadIdx.x;

    // Collapse the MLP controller to an 8-entry truth table.
    if (tid < 8) {
        const float l = (float)((tid >> 2) & 1);
        const float c = (float)((tid >> 1) & 1);
        const float r = (float)(tid & 1);
        float logit = b2[0];
#pragma unroll
        for (int h = 0; h < 16; h++) {
            float v = fmaf(l, W1[h], fmaf(c, W1[16 + h], fmaf(r, W1[32 + h], b1[h])));
            logit = fmaf(W2[h], fmaxf(v, 0.0f), logit);
        }
        smsk[tid] = (logit > 0.0f) ? ~0ULL : 0ULL;
    }
    __syncthreads();

    const u64 m0 = smsk[0], m1 = smsk[1], m2 = smsk[2], m3 = smsk[3];
    const u64 m4 = smsk[4], m5 = smsk[5], m6 = smsk[6], m7 = smsk[7];

    const int wid  = tid >> 5;                      // 0..15
    const int lane = tid & 31;
    const int half = wid >> 3;                      // 0: t<32, 1: t>=32
    const int gw   = blockIdx.x * 8 + (wid & 7);    // chunk unit 0..1023
    const int row  = gw >> 5;                       // batch row
    const int ch   = gw & (CHUNKS - 1);             // chunk within row
    const bool first = (ch == 0), last = (ch == CHUNKS - 1);

    const size_t rowoff = (size_t)row * NN;
    const int cell0 = ch * (CWORDS * 64);           // first cell of chunk

    // ---- pack this warp's chunk + halos (both halves do this) ----
    u64 cur = pack_word(f0 + rowoff + cell0 + lane * 64);
    u64 hl = 0ULL, hr = 0ULL;
    if (lane == 0 && !first)
        hl = pack_word(f0 + rowoff + cell0 - 64);
    if (lane == 31 && !last)
        hr = pack_word(f0 + rowoff + cell0 + CWORDS * 64);

    if (half == 0) {
        // t = 0 slab: copy f0 chunk verbatim (coalesced).
        const float4* src4 = (const float4*)(f0 + rowoff + cell0);
        float4* dst4 = (float4*)(out + rowoff + cell0);
#pragma unroll
        for (int k = 0; k < 16; k++)
            __stcs(dst4 + k * 32 + lane, __ldg(src4 + k * 32 + lane));

        // Steps 1..31 with stores.
        for (int t = 1; t < 32; t++) {
            ca_step(cur, hl, hr, lane, first, last, m0, m1, m2, m3, m4, m5, m6, m7);
            emit_slab(out + (size_t)t * (BB * NN) + rowoff + cell0, cur, lane);
        }
    } else {
        // Silent steps 1..31 (no stores).
        for (int t = 1; t < 32; t++)
            ca_step(cur, hl, hr, lane, first, last, m0, m1, m2, m3, m4, m5, m6, m7);

        // Steps 32..63 with stores.
        for (int t = 32; t < TT; t++) {
            ca_step(cur, hl, hr, lane, first, last, m0, m1, m2, m3, m4, m5, m6, m7);
            emit_slab(out + (size_t)t * (BB * NN) + rowoff + cell0, cur, lane);
        }
    }
}

extern "C" void kernel_launch(void* const* d_in, const int* in_sizes, int n_in,
                              void* d_out, int out_size) {
    const float* f0 = (const float*)d_in[0];
    const float* W1 = (const float*)d_in[1];
    const float* b1 = (const float*)d_in[2];
    const float* W2 = (const float*)d_in[3];
    const float* b2 = (const float*)d_in[4];
    float* out = (float*)d_out;

    // 128 CTAs x 512 threads: 16 warps/CTA = 4 per SMSP (2 of each time-half),
    // same chunk->SM placement and contiguous write streams as the champion.
    fused_kernel<<<128, 512>>>(f0, W1, b1, W2, b2, out);
}

// round 15
// speedup vs baseline: 1.1698x; 1.1503x over previous
#include <cuda_runtime.h>

// Shape fixed by setup_inputs: B=32, N=65536, T=64, HIDDEN=16.
#define BB      32
#define NN      65536
#define TT      64
#define CHUNKS  32                 // chunks per row
#define CWORDS  32                 // u64 words per chunk (2048 cells)
#define FULLM   0xFFFFFFFFu

typedef unsigned long long u64;

// 3-input mux tree over constant masks: next = msk[L*4 + C*2 + R] per bit.
__device__ __forceinline__ u64 mux3(u64 L, u64 C, u64 R,
                                    u64 m0, u64 m1, u64 m2, u64 m3,
                                    u64 m4, u64 m5, u64 m6, u64 m7) {
    u64 x0 = (R & m1) | (~R & m0);
    u64 x1 = (R & m3) | (~R & m2);
    u64 x2 = (R & m5) | (~R & m4);
    u64 x3 = (R & m7) | (~R & m6);
    u64 y0 = (C & x1) | (~C & x0);
    u64 y1 = (C & x3) | (~C & x2);
    return (L & y1) | (~L & y0);
}

__device__ __forceinline__ u64 pack_word(const float* __restrict__ p) {
    u64 w = 0ULL;
    const float4* p4 = (const float4*)p;
#pragma unroll
    for (int k = 0; k < 16; k++) {
        float4 v = p4[k];
        u64 q = 0ULL;
        if (v.x > 0.5f) q |= 1ULL;
        if (v.y > 0.5f) q |= 2ULL;
        if (v.z > 0.5f) q |= 4ULL;
        if (v.w > 0.5f) q |= 8ULL;
        w |= q << (4 * k);
    }
    return w;
}

// One warp per (row, chunk). Each lane owns one u64 word (64 cells) in a
// register; neighbor words come via warp shuffle. Lanes 0/31 additionally
// evolve one halo word each — 63 steps < 64 bits, so garbage from beyond the
// halo never reaches the chunk. Every step writes the fp32 slab for this
// chunk, coalesced via a 2-source broadcast shuffle.
__global__ __launch_bounds__(256) void fused_kernel(
    const float* __restrict__ f0,
    const float* __restrict__ W1,   // (3,16)
    const float* __restrict__ b1,   // (16,)
    const float* __restrict__ W2,   // (16,1)
    const float* __restrict__ b2,   // (1,)
    float* __restrict__ out)
{
    __shared__ u64 smsk[8];
    const int tid = threadIdx.x;

    // Collapse the MLP controller to an 8-entry truth table.
    if (tid < 8) {
        const float l = (float)((tid >> 2) & 1);
        const float c = (float)((tid >> 1) & 1);
        const float r = (float)(tid & 1);
        float logit = b2[0];
#pragma unroll
        for (int h = 0; h < 16; h++) {
            float v = fmaf(l, W1[h], fmaf(c, W1[16 + h], fmaf(r, W1[32 + h], b1[h])));
            logit = fmaf(W2[h], fmaxf(v, 0.0f), logit);
        }
        smsk[tid] = (logit > 0.0f) ? ~0ULL : 0ULL;
    }
    __syncthreads();

    const u64 m0 = smsk[0], m1 = smsk[1], m2 = smsk[2], m3 = smsk[3];
    const u64 m4 = smsk[4], m5 = smsk[5], m6 = smsk[6], m7 = smsk[7];

    const int gw   = blockIdx.x * 8 + (tid >> 5);   // global warp id 0..1023
    const int lane = tid & 31;
    const int row  = gw >> 5;                       // batch row
    const int ch   = gw & (CHUNKS - 1);             // chunk within row
    const bool first = (ch == 0), last = (ch == CHUNKS - 1);

    const size_t rowoff = (size_t)row * NN;
    const int cell0 = ch * (CWORDS * 64);           // first cell of chunk

    // ---- t = 0 slab: verbatim copy of f0 for this chunk (coalesced) ----
    const float4* src4 = (const float4*)(f0 + rowoff + cell0);
    float4* dst4 = (float4*)(out + rowoff + cell0);
#pragma unroll
    for (int k = 0; k < 16; k++) {
        __stcs(dst4 + k * 32 + lane, __ldg(src4 + k * 32 + lane));
    }

    // ---- pack this lane's word + halo words ----
    u64 cur = pack_word(f0 + rowoff + cell0 + lane * 64);
    u64 hl = 0ULL, hr = 0ULL;
    if (lane == 0 && !first)
        hl = pack_word(f0 + rowoff + cell0 - 64);
    if (lane == 31 && !last)
        hr = pack_word(f0 + rowoff + cell0 + CWORDS * 64);

    // ---- 63 CA steps, writing the fp32 slab each step ----
    for (int t = 1; t < TT; t++) {
        u64 p = __shfl_up_sync(FULLM, cur, 1);
        u64 n = __shfl_down_sync(FULLM, cur, 1);
        if (lane == 0)  p = hl;
        if (lane == 31) n = hr;

        const u64 L = (cur << 1) | (p >> 63);
        const u64 R = (cur >> 1) | (n << 63);
        const u64 nx = mux3(L, cur, R, m0, m1, m2, m3, m4, m5, m6, m7);

        // Evolve halo words (lanes 0/31 only; true row boundary stays 0).
        if (lane == 0 && !first) {
            const u64 hL = hl << 1;                       // beyond-halo = garbage-as-0
            const u64 hR = (hl >> 1) | (cur << 63);
            hl = mux3(hL, hl, hR, m0, m1, m2, m3, m4, m5, m6, m7);
        }
        if (lane == 31 && !last) {
            const u64 hL = (hr << 1) | (cur >> 63);
            const u64 hR = hr >> 1;
            hr = mux3(hL, hr, hR, m0, m1, m2, m3, m4, m5, m6, m7);
        }
        cur = nx;

        // Coalesced fp32 output: float4 #idx of the chunk comes from word
        // idx>>4 (only 2 distinct shuffle sources per iteration -> broadcast).
        float4* ot = (float4*)(out + (size_t)t * (BB * NN) + rowoff + cell0);
#pragma unroll
        for (int k = 0; k < 16; k++) {
            const int idx = k * 32 + lane;
            const u64 w = __shfl_sync(FULLM, cur, idx >> 4);
            const unsigned int nib = (unsigned int)(w >> ((idx & 15) * 4)) & 0xFu;
            float4 v;
            v.x = (nib & 1u) ? 1.0f : 0.0f;
            v.y = (nib & 2u) ? 1.0f : 0.0f;
            v.z = (nib & 4u) ? 1.0f : 0.0f;
            v.w = (nib & 8u) ? 1.0f : 0.0f;
            __stcs(ot + idx, v);
        }
    }
}

extern "C" void kernel_launch(void* const* d_in, const int* in_sizes, int n_in,
                              void* d_out, int out_size) {
    const float* f0 = (const float*)d_in[0];
    const float* W1 = (const float*)d_in[1];
    const float* b1 = (const float*)d_in[2];
    const float* W2 = (const float*)d_in[3];
    const float* b2 = (const float*)d_in[4];
    float* out = (float*)d_out;

    // 32 rows x 32 chunks = 1024 warps; 8 warps per CTA -> 128 CTAs.
    fused_kernel<<<128, 256>>>(f0, W1, b1, W2, b2, out);
}

// round 16
// speedup vs baseline: 1.1734x; 1.0031x over previous
#include <cuda_runtime.h>

// Shape fixed by setup_inputs: B=32, N=65536, T=64, HIDDEN=16.
#define BB      32
#define NN      65536
#define TT      64
#define CHUNKS  32                 // chunks per row
#define CWORDS  32                 // u64 words per chunk (2048 cells)
#define FULLM   0xFFFFFFFFu

typedef unsigned long long u64;

// 3-input mux tree over constant masks: next = msk[L*4 + C*2 + R] per bit.
__device__ __forceinline__ u64 mux3(u64 L, u64 C, u64 R,
                                    u64 m0, u64 m1, u64 m2, u64 m3,
                                    u64 m4, u64 m5, u64 m6, u64 m7) {
    u64 x0 = (R & m1) | (~R & m0);
    u64 x1 = (R & m3) | (~R & m2);
    u64 x2 = (R & m5) | (~R & m4);
    u64 x3 = (R & m7) | (~R & m6);
    u64 y0 = (C & x1) | (~C & x0);
    u64 y1 = (C & x3) | (~C & x2);
    return (L & y1) | (~L & y0);
}

__device__ __forceinline__ u64 pack_word(const float* __restrict__ p) {
    u64 w = 0ULL;
    const float4* p4 = (const float4*)p;
#pragma unroll
    for (int k = 0; k < 16; k++) {
        float4 v = p4[k];
        u64 q = 0ULL;
        if (v.x > 0.5f) q |= 1ULL;
        if (v.y > 0.5f) q |= 2ULL;
        if (v.z > 0.5f) q |= 4ULL;
        if (v.w > 0.5f) q |= 8ULL;
        w |= q << (4 * k);
    }
    return w;
}

// Emit one step's fp32 slab for the chunk (champion store path, unchanged).
__device__ __forceinline__ void emit_slab(float* __restrict__ base,
                                          u64 s, int lane) {
    float4* ot = (float4*)base;
#pragma unroll
    for (int k = 0; k < 16; k++) {
        const int idx = k * 32 + lane;
        const u64 w = __shfl_sync(FULLM, s, idx >> 4);
        const unsigned int nib = (unsigned int)(w >> ((idx & 15) * 4)) & 0xFu;
        float4 v;
        v.x = (nib & 1u) ? 1.0f : 0.0f;
        v.y = (nib & 2u) ? 1.0f : 0.0f;
        v.z = (nib & 4u) ? 1.0f : 0.0f;
        v.w = (nib & 8u) ? 1.0f : 0.0f;
        __stcs(ot + idx, v);
    }
}

// Champion structure (128 CTAs x 256 thr, u64/lane, 32-word chunks) with two
// issue-stream optimizations:
//  (1) halo words evolve in ONE unpredicated lane-parallel mux3 (companion
//      word e: lane0 carries hl, lane31 carries hr; borrow-ins gated by
//      per-lane masks; boundary lanes forced to 0 via kmask) — replaces two
//      predicated mux3 blocks.
//  (2) software pipeline: step t+1 is computed BEFORE step t's slab is
//      emitted, so stores interleave with the mux3 dependency chain.
__global__ __launch_bounds__(256) void fused_kernel(
    const float* __restrict__ f0,
    const float* __restrict__ W1,   // (3,16)
    const float* __restrict__ b1,   // (16,)
    const float* __restrict__ W2,   // (16,1)
    const float* __restrict__ b2,   // (1,)
    float* __restrict__ out)
{
    __shared__ u64 smsk[8];
    const int tid = threadIdx.x;

    // Collapse the MLP controller to an 8-entry truth table.
    if (tid < 8) {
        const float l = (float)((tid >> 2) & 1);
        const float c = (float)((tid >> 1) & 1);
        const float r = (float)(tid & 1);
        float logit = b2[0];
#pragma unroll
        for (int h = 0; h < 16; h++) {
            float v = fmaf(l, W1[h], fmaf(c, W1[16 + h], fmaf(r, W1[32 + h], b1[h])));
            logit = fmaf(W2[h], fmaxf(v, 0.0f), logit);
        }
        smsk[tid] = (logit > 0.0f) ? ~0ULL : 0ULL;
    }
    __syncthreads();

    const u64 m0 = smsk[0], m1 = smsk[1], m2 = smsk[2], m3 = smsk[3];
    const u64 m4 = smsk[4], m5 = smsk[5], m6 = smsk[6], m7 = smsk[7];

    const int gw   = blockIdx.x * 8 + (tid >> 5);   // global warp id 0..1023
    const int lane = tid & 31;
    const int row  = gw >> 5;                       // batch row
    const int ch   = gw & (CHUNKS - 1);             // chunk within row
    const bool first = (ch == 0), last = (ch == CHUNKS - 1);

    const size_t rowoff = (size_t)row * NN;
    const int cell0 = ch * (CWORDS * 64);           // first cell of chunk

    // ---- t = 0 slab: verbatim copy of f0 for this chunk (coalesced) ----
    const float4* src4 = (const float4*)(f0 + rowoff + cell0);
    float4* dst4 = (float4*)(out + rowoff + cell0);
#pragma unroll
    for (int k = 0; k < 16; k++)
        __stcs(dst4 + k * 32 + lane, __ldg(src4 + k * 32 + lane));

    // ---- pack this lane's word + companion halo word e ----
    u64 cur = pack_word(f0 + rowoff + cell0 + lane * 64);
    u64 e = 0ULL;
    if (lane == 0 && !first)
        e = pack_word(f0 + rowoff + cell0 - 64);          // hl
    if (lane == 31 && !last)
        e = pack_word(f0 + rowoff + cell0 + CWORDS * 64); // hr

    // Per-lane constant masks for the companion-word recurrence.
    const u64 m0s   = (lane == 0  && !first) ? ~0ULL : 0ULL; // lane0 takes cur<<63 into eR
    const u64 m31s  = (lane == 31 && !last)  ? ~0ULL : 0ULL; // lane31 takes cur>>63 into eL
    const u64 kmask = ((lane == 0 && first) || (lane == 31 && last)) ? 0ULL : ~0ULL;

    // One CA step: advances cur and e together.
#define CA_STEP()                                                            \
    do {                                                                     \
        u64 p = __shfl_up_sync(FULLM, cur, 1);                               \
        u64 n = __shfl_down_sync(FULLM, cur, 1);                             \
        if (lane == 0)  p = e;                                               \
        if (lane == 31) n = e;                                               \
        const u64 L  = (cur << 1) | (p >> 63);                               \
        const u64 R  = (cur >> 1) | (n << 63);                               \
        const u64 eL = (e << 1) | ((cur >> 63) & m31s);                      \
        const u64 eR = (e >> 1) | ((cur << 63) & m0s);                       \
        const u64 ne = mux3(eL, e, eR, m0, m1, m2, m3, m4, m5, m6, m7) & kmask; \
        const u64 nx = mux3(L, cur, R, m0, m1, m2, m3, m4, m5, m6, m7);      \
        cur = nx;                                                            \
        e = ne;                                                              \
    } while (0)

    // ---- 63 CA steps, pipelined: compute t+1 before storing t's slab ----
    CA_STEP();                                      // cur = state at t=1
    for (int t = 1; t < TT - 1; t++) {
        const u64 old = cur;
        CA_STEP();                                  // cur = state at t+1
        emit_slab(out + (size_t)t * (BB * NN) + rowoff + cell0, old, lane);
    }
    emit_slab(out + (size_t)(TT - 1) * (BB * NN) + rowoff + cell0, cur, lane);
#undef CA_STEP
}

extern "C" void kernel_launch(void* const* d_in, const int* in_sizes, int n_in,
                              void* d_out, int out_size) {
    const float* f0 = (const float*)d_in[0];
    const float* W1 = (const float*)d_in[1];
    const float* b1 = (const float*)d_in[2];
    const float* W2 = (const float*)d_in[3];
    const float* b2 = (const float*)d_in[4];
    float* out = (float*)d_out;

    // Champion launch shape: 32 rows x 32 chunks = 1024 warps,
    // 8 warps per CTA -> 128 CTAs (2 warps per SMSP, balanced).
    fused_kernel<<<128, 256>>>(f0, W1, b1, W2, b2, out);
}